// round 14
// baseline (speedup 1.0000x reference)
#include <cuda_runtime.h>
#include <math_constants.h>

// Problem constants (fixed by the dataset reference)
#define BATCH   8
#define NPTS    16384
#define MPTS    4096
#define CS      256
#define CF      128
#define COUT    (CS + CF)

// 8x8x8 spatial grid: cell edge 0.825 ~ 1.7x typical k3 distance
#define NC_D    8
#define NCELLS  512
#define GRANGE  3.3f
#define CELL    (2.0f * GRANGE / NC_D)
#define GINV    (NC_D / (2.0f * GRANGE))

// Scratch (__device__ globals; no allocation)
__device__ float4 g_ct[BATCH * MPTS];            // cell-grouped (x,y,z,0.5|y|^2)
__device__ int    g_ci[BATCH * MPTS];            // original candidate index
__device__ int    g_cs[BATCH * (NCELLS + 1)];    // cell start offsets
__device__ int    g_qo[BATCH * NPTS];            // queries grouped by cell
__device__ int2   g_top[BATCH * NPTS * 3];       // {d_bits, orig idx} per query

__device__ __forceinline__ int clampi(int v, int lo, int hi) {
    return min(hi, max(lo, v));
}
__device__ __forceinline__ void cell_xyz(float x, float y, float z,
                                         int& cx, int& cy, int& cz) {
    cx = clampi((int)((x + GRANGE) * GINV), 0, NC_D - 1);
    cy = clampi((int)((y + GRANGE) * GINV), 0, NC_D - 1);
    cz = clampi((int)((z + GRANGE) * GINV), 0, NC_D - 1);
}

// ---------------------------------------------------------------------------
// K1: group candidates by cell. 1 CTA per batch.
// ---------------------------------------------------------------------------
__global__ __launch_bounds__(256)
void cand_group_kernel(const float* __restrict__ sxyz)
{
    __shared__ int cnt[NCELLS];
    __shared__ int off[NCELLS];
    const int b = blockIdx.x, tid = threadIdx.x;
    const float* yb = sxyz + (size_t)b * MPTS * 3;

    for (int i = tid; i < NCELLS; i += 256) cnt[i] = 0;
    __syncthreads();
    for (int i = tid; i < MPTS; i += 256) {
        int cx, cy, cz;
        cell_xyz(yb[i*3], yb[i*3+1], yb[i*3+2], cx, cy, cz);
        atomicAdd(&cnt[(cz * NC_D + cy) * NC_D + cx], 1);
    }
    __syncthreads();
    if (tid == 0) {
        int s = 0;
        for (int c = 0; c < NCELLS; c++) {
            off[c] = s; g_cs[b * (NCELLS + 1) + c] = s; s += cnt[c];
        }
        g_cs[b * (NCELLS + 1) + NCELLS] = s;
    }
    __syncthreads();
    for (int i = tid; i < MPTS; i += 256) {
        const float y0 = yb[i*3], y1 = yb[i*3+1], y2 = yb[i*3+2];
        int cx, cy, cz;
        cell_xyz(y0, y1, y2, cx, cy, cz);
        const int p = atomicAdd(&off[(cz * NC_D + cy) * NC_D + cx], 1);
        g_ct[b * MPTS + p] = make_float4(y0, y1, y2, 0.5f * (y0*y0 + y1*y1 + y2*y2));
        g_ci[b * MPTS + p] = i;
    }
}

// ---------------------------------------------------------------------------
// K2: group queries by cell (order within cell arbitrary; outputs per-query
// so grouping order never affects results). 1 CTA per batch.
// ---------------------------------------------------------------------------
__global__ __launch_bounds__(256)
void query_group_kernel(const float* __restrict__ xyz)
{
    __shared__ int cnt[NCELLS];
    __shared__ int off[NCELLS];
    const int b = blockIdx.x, tid = threadIdx.x;
    const float* xb = xyz + (size_t)b * NPTS * 3;

    for (int i = tid; i < NCELLS; i += 256) cnt[i] = 0;
    __syncthreads();
    for (int n = tid; n < NPTS; n += 256) {
        int cx, cy, cz;
        cell_xyz(xb[n*3], xb[n*3+1], xb[n*3+2], cx, cy, cz);
        atomicAdd(&cnt[(cz * NC_D + cy) * NC_D + cx], 1);
    }
    __syncthreads();
    if (tid == 0) {
        int s = 0;
        for (int c = 0; c < NCELLS; c++) { off[c] = s; s += cnt[c]; }
    }
    __syncthreads();
    for (int n = tid; n < NPTS; n += 256) {
        int cx, cy, cz;
        cell_xyz(xb[n*3], xb[n*3+1], xb[n*3+2], cx, cy, cz);
        g_qo[b * NPTS + atomicAdd(&off[(cz * NC_D + cy) * NC_D + cx], 1)] = n;
    }
}

// ---------------------------------------------------------------------------
// K3: exact 3-NN via expanding Chebyshev shells around the warp's home cell.
// Thread per query; grid (128, BATCH) x 128 thr; candidates via broadcast LDG.
// ---------------------------------------------------------------------------
__global__ __launch_bounds__(128)
void knn_kernel(const float* __restrict__ xyz)
{
    __shared__ int cstart[NCELLS + 1];
    const int b   = blockIdx.y;
    const int tid = threadIdx.x;
    const float4* ct = g_ct + b * MPTS;

    for (int i = tid; i <= NCELLS; i += 128)
        cstart[i] = g_cs[b * (NCELLS + 1) + i];
    __syncthreads();

    const int n = g_qo[b * NPTS + blockIdx.x * 128 + tid];
    const float* xq = xyz + ((size_t)b * NPTS + n) * 3;
    const float x0 = xq[0], x1 = xq[1], x2 = xq[2];
    const float nx = -x0, ny = -x1, nz = -x2;
    const float xn2 = x0*x0 + x1*x1 + x2*x2;

    int qcx, qcy, qcz;
    cell_xyz(x0, x1, x2, qcx, qcy, qcz);

    // warp home cell = lane 0's cell (queries are cell-grouped)
    int home = (qcz * NC_D + qcy) * NC_D + qcx;
    home = __shfl_sync(0xFFFFFFFFu, home, 0);
    const int hx_ = home & (NC_D - 1);
    const int hy_ = (home >> 3) & (NC_D - 1);
    const int hz_ = home >> 6;

    float S0 = CUDART_INF_F, S1 = CUDART_INF_F, S2 = CUDART_INF_F;
    int   I0 = 0, I1 = 0, I2 = 0;

    for (int rho = 0; rho <= NC_D; rho++) {
        const int zlo = max(0, hz_ - rho), zhi = min(NC_D - 1, hz_ + rho);
        const int ylo = max(0, hy_ - rho), yhi = min(NC_D - 1, hy_ + rho);
        const int xlo = max(0, hx_ - rho), xhi = min(NC_D - 1, hx_ + rho);

        for (int cz = zlo; cz <= zhi; cz++)
        for (int cy = ylo; cy <= yhi; cy++)
        for (int cx = xlo; cx <= xhi; cx++) {
            const int ch = max(abs(cz - hz_), max(abs(cy - hy_), abs(cx - hx_)));
            if (ch != rho) continue;                      // only this shell
            const int c   = (cz * NC_D + cy) * NC_D + cx;
            const int beg = cstart[c], end = cstart[c + 1];
            if (beg == end) continue;

            // exact point-to-cell lower bound (edge cells extend to infinity)
            const float clx = (cx == 0)        ? -CUDART_INF_F : -GRANGE + cx * CELL;
            const float chx = (cx == NC_D - 1) ?  CUDART_INF_F : -GRANGE + (cx + 1) * CELL;
            const float cly = (cy == 0)        ? -CUDART_INF_F : -GRANGE + cy * CELL;
            const float chy = (cy == NC_D - 1) ?  CUDART_INF_F : -GRANGE + (cy + 1) * CELL;
            const float clz = (cz == 0)        ? -CUDART_INF_F : -GRANGE + cz * CELL;
            const float chz = (cz == NC_D - 1) ?  CUDART_INF_F : -GRANGE + (cz + 1) * CELL;
            const float t0 = fmaxf(fmaxf(clx - x0, x0 - chx), 0.0f);
            const float t1 = fmaxf(fmaxf(cly - x1, x1 - chy), 0.0f);
            const float t2 = fmaxf(fmaxf(clz - x2, x2 - chz), 0.0f);
            const float db2 = fmaf(t0, t0, fmaf(t1, t1, t2 * t2));
            const float D2  = fmaf(2.0f, S2, xn2);        // inf-safe threshold

            if (!__any_sync(0xFFFFFFFFu, db2 < D2)) continue;

            for (int j = beg; j < end; j++) {
                const float4 y = __ldg(&ct[j]);           // broadcast LDG.128
                const float s = fmaf(y.x, nx, fmaf(y.y, ny, fmaf(y.z, nz, y.w)));
                if (s < S2) {
                    if (s < S1) {
                        S2 = S1; I2 = I1;
                        if (s < S0) { S1 = S0; I1 = I0; S0 = s; I0 = j; }
                        else        { S1 = s;  I1 = j; }
                    } else { S2 = s; I2 = j; }
                }
            }
        }

        // stop test: distance from each lane's point to the region beyond the
        // (2*rho+1)^3 box around home; grid-edge faces have nothing beyond.
        const float fxl = (hx_ - rho <= 0)        ? CUDART_INF_F
                        : fmaxf(x0 - (-GRANGE + (hx_ - rho) * CELL), 0.0f);
        const float fxh = (hx_ + rho >= NC_D - 1) ? CUDART_INF_F
                        : fmaxf((-GRANGE + (hx_ + rho + 1) * CELL) - x0, 0.0f);
        const float fyl = (hy_ - rho <= 0)        ? CUDART_INF_F
                        : fmaxf(x1 - (-GRANGE + (hy_ - rho) * CELL), 0.0f);
        const float fyh = (hy_ + rho >= NC_D - 1) ? CUDART_INF_F
                        : fmaxf((-GRANGE + (hy_ + rho + 1) * CELL) - x1, 0.0f);
        const float fzl = (hz_ - rho <= 0)        ? CUDART_INF_F
                        : fmaxf(x2 - (-GRANGE + (hz_ - rho) * CELL), 0.0f);
        const float fzh = (hz_ + rho >= NC_D - 1) ? CUDART_INF_F
                        : fmaxf((-GRANGE + (hz_ + rho + 1) * CELL) - x2, 0.0f);
        const float od  = fminf(fminf(fminf(fxl, fxh), fminf(fyl, fyh)),
                                fminf(fzl, fzh));
        const float D2  = fmaf(2.0f, S2, xn2);
        if (__all_sync(0xFFFFFFFFu, od * od >= D2 && od == od && D2 < CUDART_INF_F))
            break;
    }

    const size_t o = ((size_t)b * NPTS + n) * 3;
    g_top[o + 0] = make_int2(__float_as_int(fmaf(2.0f, S0, xn2)), g_ci[b*MPTS + I0]);
    g_top[o + 1] = make_int2(__float_as_int(fmaf(2.0f, S1, xn2)), g_ci[b*MPTS + I1]);
    g_top[o + 2] = make_int2(__float_as_int(fmaf(2.0f, S2, xn2)), g_ci[b*MPTS + I2]);
}

// ---------------------------------------------------------------------------
// K4: warp-per-query weights + gather + interp + concat. Grid (2048, 8).
// ---------------------------------------------------------------------------
__global__ __launch_bounds__(256)
void interp_kernel(const float* __restrict__ feat,
                   const float* __restrict__ sfeat,
                   float* __restrict__ out)
{
    const int b    = blockIdx.y;
    const int warp = threadIdx.x >> 5;
    const int lane = threadIdx.x & 31;
    const int n    = blockIdx.x * 8 + warp;

    int2 t = make_int2(0, 0);
    if (lane < 3) t = g_top[((size_t)b * NPTS + n) * 3 + lane];

    float dd[3]; int ii[3];
    #pragma unroll
    for (int r = 0; r < 3; r++) {
        dd[r] = __int_as_float(__shfl_sync(0xFFFFFFFFu, t.x, r));
        ii[r] = __shfl_sync(0xFFFFFFFFu, t.y, r);
    }

    float d0 = fmaxf(dd[0], 1e-10f);
    float d1 = fmaxf(dd[1], 1e-10f);
    float d2 = fmaxf(dd[2], 1e-10f);
    float w0 = 1.0f / (d0 * d0 + 1e-7f);
    float w1 = 1.0f / (d1 * d1 + 1e-7f);
    float w2 = 1.0f / (d2 * d2 + 1e-7f);
    const float inv = 1.0f / (w0 + w1 + w2 + 1e-10f);
    w0 *= inv; w1 *= inv; w2 *= inv;

    const float4* sfb = (const float4*)(sfeat + (size_t)b * MPTS * CS);
    const float4* fb  = (const float4*)(feat  + (size_t)b * NPTS * CF);
    float4*       ob  = (float4*)(out + (size_t)b * NPTS * COUT);

    const float4* r0 = sfb + (size_t)ii[0] * (CS / 4);
    const float4* r1 = sfb + (size_t)ii[1] * (CS / 4);
    const float4* r2 = sfb + (size_t)ii[2] * (CS / 4);
    float4* o = ob + (size_t)n * (COUT / 4);

    #pragma unroll
    for (int c = lane; c < CS / 4; c += 32) {
        const float4 a = r0[c];
        const float4 d = r1[c];
        const float4 e = r2[c];
        float4 rv;
        rv.x = w0 * a.x + w1 * d.x + w2 * e.x;
        rv.y = w0 * a.y + w1 * d.y + w2 * e.y;
        rv.z = w0 * a.z + w1 * d.z + w2 * e.z;
        rv.w = w0 * a.w + w1 * d.w + w2 * e.w;
        o[c] = rv;
    }
    const float4* f = fb + (size_t)n * (CF / 4);
    o[CS / 4 + lane] = f[lane];
}

extern "C" void kernel_launch(void* const* d_in, const int* in_sizes, int n_in,
                              void* d_out, int out_size)
{
    const float* xyz   = (const float*)d_in[0];
    const float* sxyz  = (const float*)d_in[1];
    const float* feat  = (const float*)d_in[2];
    const float* sfeat = (const float*)d_in[3];
    float* out = (float*)d_out;

    cand_group_kernel<<<BATCH, 256>>>(sxyz);
    query_group_kernel<<<BATCH, 256>>>(xyz);
    dim3 g3(NPTS / 128, BATCH);
    knn_kernel<<<g3, 128>>>(xyz);
    dim3 g4(NPTS / 8, BATCH);
    interp_kernel<<<g4, 256>>>(feat, sfeat, out);
}

// round 15
// speedup vs baseline: 1.2300x; 1.2300x over previous
#include <cuda_runtime.h>
#include <math_constants.h>

// Problem constants (fixed by the dataset reference)
#define BATCH   8
#define NPTS    16384
#define MPTS    4096
#define CS      256
#define CF      128
#define COUT    (CS + CF)

// 8x8x8 grid; cell edge 0.825 >> typical d3 (~0.2)
#define NC_D    8
#define NCELLS  512
#define GRANGE  3.3f
#define CELL    (2.0f * GRANGE / NC_D)
#define GINV    (NC_D / (2.0f * GRANGE))
#define QSLOTS  32768                     // warp-aligned padded query slots/batch

// Scratch (__device__ globals; no allocation)
__device__ float4 g_ct[BATCH * MPTS];            // cell-grouped (x,y,z,0.5|y|^2)
__device__ int    g_ci[BATCH * MPTS];            // original candidate index
__device__ int    g_cs[BATCH * (NCELLS + 1)];    // candidate cell offsets
__device__ int    g_qo[BATCH * QSLOTS];          // padded queries (-1 = idle)
__device__ int2   g_top[BATCH * NPTS * 3];       // {d_bits, orig idx} per query

__device__ __forceinline__ int clampi(int v, int lo, int hi) {
    return min(hi, max(lo, v));
}
__device__ __forceinline__ void cell_xyz(float x, float y, float z,
                                         int& cx, int& cy, int& cz) {
    cx = clampi((int)((x + GRANGE) * GINV), 0, NC_D - 1);
    cy = clampi((int)((y + GRANGE) * GINV), 0, NC_D - 1);
    cz = clampi((int)((z + GRANGE) * GINV), 0, NC_D - 1);
}

// ---------------------------------------------------------------------------
// K1: group candidates by cell. 1 CTA per batch, 512 thr.
// ---------------------------------------------------------------------------
__global__ __launch_bounds__(512)
void cand_group_kernel(const float* __restrict__ sxyz)
{
    __shared__ int cnt[NCELLS];
    __shared__ int off[NCELLS];
    const int b = blockIdx.x, tid = threadIdx.x;
    const float* yb = sxyz + (size_t)b * MPTS * 3;

    if (tid < NCELLS) cnt[tid] = 0;
    __syncthreads();
    for (int i = tid; i < MPTS; i += 512) {
        int cx, cy, cz;
        cell_xyz(yb[i*3], yb[i*3+1], yb[i*3+2], cx, cy, cz);
        atomicAdd(&cnt[(cz * NC_D + cy) * NC_D + cx], 1);
    }
    __syncthreads();
    if (tid == 0) {
        int s = 0;
        for (int c = 0; c < NCELLS; c++) {
            off[c] = s; g_cs[b * (NCELLS + 1) + c] = s; s += cnt[c];
        }
        g_cs[b * (NCELLS + 1) + NCELLS] = s;
    }
    __syncthreads();
    for (int i = tid; i < MPTS; i += 512) {
        const float y0 = yb[i*3], y1 = yb[i*3+1], y2 = yb[i*3+2];
        int cx, cy, cz;
        cell_xyz(y0, y1, y2, cx, cy, cz);
        const int p = atomicAdd(&off[(cz * NC_D + cy) * NC_D + cx], 1);
        g_ct[b * MPTS + p] = make_float4(y0, y1, y2, 0.5f * (y0*y0 + y1*y1 + y2*y2));
        g_ci[b * MPTS + p] = i;
    }
}

// ---------------------------------------------------------------------------
// K2: group queries by cell into WARP-ALIGNED slots (pad to 32 with -1).
// Guarantees every warp of K3 is cell-pure. 1 CTA per batch, 512 thr.
// ---------------------------------------------------------------------------
__global__ __launch_bounds__(512)
void query_group_kernel(const float* __restrict__ xyz)
{
    __shared__ int cnt[NCELLS];
    __shared__ int off[NCELLS];
    const int b = blockIdx.x, tid = threadIdx.x;
    const float* xb = xyz + (size_t)b * NPTS * 3;

    for (int i = tid; i < QSLOTS; i += 512) g_qo[b * QSLOTS + i] = -1;
    if (tid < NCELLS) cnt[tid] = 0;
    __syncthreads();
    for (int n = tid; n < NPTS; n += 512) {
        int cx, cy, cz;
        cell_xyz(xb[n*3], xb[n*3+1], xb[n*3+2], cx, cy, cz);
        atomicAdd(&cnt[(cz * NC_D + cy) * NC_D + cx], 1);
    }
    __syncthreads();
    if (tid == 0) {
        int s = 0;
        for (int c = 0; c < NCELLS; c++) {
            off[c] = s;
            s += (cnt[c] + 31) & ~31;     // warp-aligned group starts
        }
    }
    __syncthreads();
    for (int n = tid; n < NPTS; n += 512) {
        int cx, cy, cz;
        cell_xyz(xb[n*3], xb[n*3+1], xb[n*3+2], cx, cy, cz);
        const int p = atomicAdd(&off[(cz * NC_D + cy) * NC_D + cx], 1);
        g_qo[b * QSLOTS + p] = n;
    }
}

// ---------------------------------------------------------------------------
// K3: exact 3-NN. Each warp (cell-pure) scans the fixed 27-cell neighborhood;
// lanes whose k3 bound exceeds the box margin trigger a warp full rescan.
// Grid (QSLOTS/128, BATCH) x 128 thr.
// ---------------------------------------------------------------------------
__global__ __launch_bounds__(128)
void knn_kernel(const float* __restrict__ xyz)
{
    __shared__ int cstart[NCELLS + 1];
    const int b   = blockIdx.y;
    const int tid = threadIdx.x;
    const float4* ct = g_ct + b * MPTS;

    for (int i = tid; i <= NCELLS; i += 128)
        cstart[i] = g_cs[b * (NCELLS + 1) + i];
    __syncthreads();

    const int slot = blockIdx.x * 128 + tid;
    const int n    = g_qo[b * QSLOTS + slot];
    if (__all_sync(0xFFFFFFFFu, n < 0)) return;     // fully idle warp

    // home cell from lane 0 (warp is cell-pure; lane 0 always real)
    float x0, x1, x2;
    int hx_, hy_, hz_;
    {
        const int n0 = __shfl_sync(0xFFFFFFFFu, n, 0);
        if (n >= 0) {
            const float* xq = xyz + ((size_t)b * NPTS + n) * 3;
            x0 = xq[0]; x1 = xq[1]; x2 = xq[2];
        }
        float h0 = __shfl_sync(0xFFFFFFFFu, x0, 0);
        float h1 = __shfl_sync(0xFFFFFFFFu, x1, 0);
        float h2 = __shfl_sync(0xFFFFFFFFu, x2, 0);
        cell_xyz(h0, h1, h2, hx_, hy_, hz_);
        if (n < 0) {   // idle lane: home-cell center (uniform, harmless work)
            x0 = -GRANGE + (hx_ + 0.5f) * CELL;
            x1 = -GRANGE + (hy_ + 0.5f) * CELL;
            x2 = -GRANGE + (hz_ + 0.5f) * CELL;
        }
        (void)n0;
    }
    const float nx = -x0, ny = -x1, nz = -x2;
    const float xn2 = x0*x0 + x1*x1 + x2*x2;

    float S0 = CUDART_INF_F, S1 = CUDART_INF_F, S2 = CUDART_INF_F;
    int   I0 = 0, I1 = 0, I2 = 0;

    // -------- fixed 27-cell neighborhood scan (warp-uniform) ---------------
    const int zlo = max(0, hz_ - 1), zhi = min(NC_D - 1, hz_ + 1);
    const int ylo = max(0, hy_ - 1), yhi = min(NC_D - 1, hy_ + 1);
    const int xlo = max(0, hx_ - 1), xhi = min(NC_D - 1, hx_ + 1);
    for (int cz = zlo; cz <= zhi; cz++)
    for (int cy = ylo; cy <= yhi; cy++) {
        const int crow = (cz * NC_D + cy) * NC_D;
        const int beg = cstart[crow + xlo];
        const int end = cstart[crow + xhi + 1];    // x-contiguous: one segment
        for (int j = beg; j < end; j++) {
            const float4 y = __ldg(&ct[j]);        // broadcast LDG.128
            const float s = fmaf(y.x, nx, fmaf(y.y, ny, fmaf(y.z, nz, y.w)));
            if (s < S2) {
                if (s < S1) {
                    S2 = S1; I2 = I1;
                    if (s < S0) { S1 = S0; I1 = I0; S0 = s; I0 = j; }
                    else        { S1 = s;  I1 = j; }
                } else { S2 = s; I2 = j; }
            }
        }
    }

    // -------- exactness check: k3 distance vs distance to box boundary -----
    const float fxl = (hx_ - 1 <= 0)        ? CUDART_INF_F
                    : fmaxf(x0 - (-GRANGE + (hx_ - 1) * CELL), 0.0f);
    const float fxh = (hx_ + 1 >= NC_D - 1) ? CUDART_INF_F
                    : fmaxf((-GRANGE + (hx_ + 2) * CELL) - x0, 0.0f);
    const float fyl = (hy_ - 1 <= 0)        ? CUDART_INF_F
                    : fmaxf(x1 - (-GRANGE + (hy_ - 1) * CELL), 0.0f);
    const float fyh = (hy_ + 1 >= NC_D - 1) ? CUDART_INF_F
                    : fmaxf((-GRANGE + (hy_ + 2) * CELL) - x1, 0.0f);
    const float fzl = (hz_ - 1 <= 0)        ? CUDART_INF_F
                    : fmaxf(x2 - (-GRANGE + (hz_ - 1) * CELL), 0.0f);
    const float fzh = (hz_ + 1 >= NC_D - 1) ? CUDART_INF_F
                    : fmaxf((-GRANGE + (hz_ + 2) * CELL) - x2, 0.0f);
    const float margin = fminf(fminf(fminf(fxl, fxh), fminf(fyl, fyh)),
                               fminf(fzl, fzh));
    const float D2 = fmaf(2.0f, S2, xn2);
    const bool need_full = (n >= 0) && !(margin * margin >= D2);

    if (__any_sync(0xFFFFFFFFu, need_full)) {
        // rare: full exact rescan from scratch (no duplicate inserts)
        S0 = CUDART_INF_F; S1 = CUDART_INF_F; S2 = CUDART_INF_F;
        I0 = 0; I1 = 0; I2 = 0;
        for (int j = 0; j < MPTS; j++) {
            const float4 y = __ldg(&ct[j]);
            const float s = fmaf(y.x, nx, fmaf(y.y, ny, fmaf(y.z, nz, y.w)));
            if (s < S2) {
                if (s < S1) {
                    S2 = S1; I2 = I1;
                    if (s < S0) { S1 = S0; I1 = I0; S0 = s; I0 = j; }
                    else        { S1 = s;  I1 = j; }
                } else { S2 = s; I2 = j; }
            }
        }
    }

    if (n >= 0) {
        const size_t o = ((size_t)b * NPTS + n) * 3;
        g_top[o + 0] = make_int2(__float_as_int(fmaf(2.0f, S0, xn2)), g_ci[b*MPTS + I0]);
        g_top[o + 1] = make_int2(__float_as_int(fmaf(2.0f, S1, xn2)), g_ci[b*MPTS + I1]);
        g_top[o + 2] = make_int2(__float_as_int(fmaf(2.0f, S2, xn2)), g_ci[b*MPTS + I2]);
    }
}

// ---------------------------------------------------------------------------
// K4: warp-per-query weights + gather + interp + concat. Grid (2048, 8).
// ---------------------------------------------------------------------------
__global__ __launch_bounds__(256)
void interp_kernel(const float* __restrict__ feat,
                   const float* __restrict__ sfeat,
                   float* __restrict__ out)
{
    const int b    = blockIdx.y;
    const int warp = threadIdx.x >> 5;
    const int lane = threadIdx.x & 31;
    const int n    = blockIdx.x * 8 + warp;

    int2 t = make_int2(0, 0);
    if (lane < 3) t = g_top[((size_t)b * NPTS + n) * 3 + lane];

    float dd[3]; int ii[3];
    #pragma unroll
    for (int r = 0; r < 3; r++) {
        dd[r] = __int_as_float(__shfl_sync(0xFFFFFFFFu, t.x, r));
        ii[r] = __shfl_sync(0xFFFFFFFFu, t.y, r);
    }

    float d0 = fmaxf(dd[0], 1e-10f);
    float d1 = fmaxf(dd[1], 1e-10f);
    float d2 = fmaxf(dd[2], 1e-10f);
    float w0 = 1.0f / (d0 * d0 + 1e-7f);
    float w1 = 1.0f / (d1 * d1 + 1e-7f);
    float w2 = 1.0f / (d2 * d2 + 1e-7f);
    const float inv = 1.0f / (w0 + w1 + w2 + 1e-10f);
    w0 *= inv; w1 *= inv; w2 *= inv;

    const float4* sfb = (const float4*)(sfeat + (size_t)b * MPTS * CS);
    const float4* fb  = (const float4*)(feat  + (size_t)b * NPTS * CF);
    float4*       ob  = (float4*)(out + (size_t)b * NPTS * COUT);

    const float4* r0 = sfb + (size_t)ii[0] * (CS / 4);
    const float4* r1 = sfb + (size_t)ii[1] * (CS / 4);
    const float4* r2 = sfb + (size_t)ii[2] * (CS / 4);
    float4* o = ob + (size_t)n * (COUT / 4);

    #pragma unroll
    for (int c = lane; c < CS / 4; c += 32) {
        const float4 a = r0[c];
        const float4 d = r1[c];
        const float4 e = r2[c];
        float4 rv;
        rv.x = w0 * a.x + w1 * d.x + w2 * e.x;
        rv.y = w0 * a.y + w1 * d.y + w2 * e.y;
        rv.z = w0 * a.z + w1 * d.z + w2 * e.z;
        rv.w = w0 * a.w + w1 * d.w + w2 * e.w;
        o[c] = rv;
    }
    const float4* f = fb + (size_t)n * (CF / 4);
    o[CS / 4 + lane] = f[lane];
}

extern "C" void kernel_launch(void* const* d_in, const int* in_sizes, int n_in,
                              void* d_out, int out_size)
{
    const float* xyz   = (const float*)d_in[0];
    const float* sxyz  = (const float*)d_in[1];
    const float* feat  = (const float*)d_in[2];
    const float* sfeat = (const float*)d_in[3];
    float* out = (float*)d_out;

    cand_group_kernel<<<BATCH, 512>>>(sxyz);
    query_group_kernel<<<BATCH, 512>>>(xyz);
    dim3 g3(QSLOTS / 128, BATCH);
    knn_kernel<<<g3, 128>>>(xyz);
    dim3 g4(NPTS / 8, BATCH);
    interp_kernel<<<g4, 256>>>(feat, sfeat, out);
}